// round 2
// baseline (speedup 1.0000x reference)
#include <cuda_runtime.h>
#include <math.h>

// ---------------------------------------------------------------------------
// DOSAConLoss: fused CIoU localization loss + pairwise contrastive loss.
//
// KEY INSIGHT: reference's saf_ciou = (1-ciou)^2.5 [shape (N,1)] / area [shape
// (N,)] broadcasts to (N,N); the (N,N) mean FACTORIZES:
//   loss_loc = (Sum_i dw_i*hw_i*(1-ciou_i)^2.5) * (Sum_j 1/(area_j+1e-7)) / N^2
//
// Inputs (metadata order):
//   d_in[0] : pred_boxes   float32 [N,4]   (x,y,w,h)
//   d_in[1] : target_boxes float32 [N,4]
//   d_in[2] : embeddings   float32 [N,D]   (D=256)
//   d_in[3] : density_map  float32 [N]
//   d_in[4] : indices      int32   [P,2]
//   d_out   : float32 scalar
// ---------------------------------------------------------------------------

#define EPSF        1e-7f
#define ALPHA_C     1.2f
#define TAU_C       0.3f
#define DELTA_C     1.0f
#define FOUR_PI2    0.40528473456935108577f   // 4/pi^2

#define LOC_THREADS 256
#define MAX_PART    1024

__device__ float g_partA[MAX_PART];   // loc numerator partials
__device__ float g_partB[MAX_PART];   // loc 1/area partials
__device__ float g_partC[MAX_PART];   // contrastive partials

// ---- fused block reduce of two floats ----
__device__ __forceinline__ float2 block_reduce_sum2(float a, float b) {
    __shared__ float shA[LOC_THREADS / 32];
    __shared__ float shB[LOC_THREADS / 32];
    int lane = threadIdx.x & 31;
    int warp = threadIdx.x >> 5;
    #pragma unroll
    for (int off = 16; off > 0; off >>= 1) {
        a += __shfl_down_sync(0xffffffffu, a, off);
        b += __shfl_down_sync(0xffffffffu, b, off);
    }
    if (lane == 0) { shA[warp] = a; shB[warp] = b; }
    __syncthreads();
    int nw = blockDim.x >> 5;
    a = (threadIdx.x < nw) ? shA[threadIdx.x] : 0.0f;
    b = (threadIdx.x < nw) ? shB[threadIdx.x] : 0.0f;
    if (warp == 0) {
        #pragma unroll
        for (int off = 16; off > 0; off >>= 1) {
            a += __shfl_down_sync(0xffffffffu, a, off);
            b += __shfl_down_sync(0xffffffffu, b, off);
        }
    }
    return make_float2(a, b);   // valid in thread 0
}

// ---- plain IoU of two (x,y,w,h) boxes ----
__device__ __forceinline__ float plain_iou(float4 a, float4 b) {
    float a_x1 = a.x - a.z * 0.5f, a_x2 = a.x + a.z * 0.5f;
    float a_y1 = a.y - a.w * 0.5f, a_y2 = a.y + a.w * 0.5f;
    float b_x1 = b.x - b.z * 0.5f, b_x2 = b.x + b.z * 0.5f;
    float b_y1 = b.y - b.w * 0.5f, b_y2 = b.y + b.w * 0.5f;
    float iw = fmaxf(fminf(a_x2, b_x2) - fmaxf(a_x1, b_x1), 0.0f);
    float ih = fmaxf(fminf(a_y2, b_y2) - fmaxf(a_y1, b_y1), 0.0f);
    float inter = iw * ih;
    float uni = a.z * a.w + b.z * b.w - inter + EPSF;
    return inter / uni;
}

__global__ void dosa_fused_kernel(const float4* __restrict__ pred,
                                  const float4* __restrict__ tgt,
                                  const float*  __restrict__ emb,
                                  const float*  __restrict__ dens,
                                  const int*    __restrict__ idx,
                                  int N, int D, int P, int locBlocks) {
    if ((int)blockIdx.x < locBlocks) {
        // ---------------- localization term (two factorized sums) ----------
        float accA = 0.0f;   // dw*hw*(1-ciou)^2.5
        float accB = 0.0f;   // 1/(area+1e-7)
        int i = blockIdx.x * blockDim.x + threadIdx.x;
        if (i < N) {
            float4 b1 = pred[i];
            float4 b2 = tgt[i];

            float w1 = b1.z, h1 = b1.w, w2 = b2.z, h2 = b2.w;
            float b1x1 = b1.x - w1 * 0.5f, b1x2 = b1.x + w1 * 0.5f;
            float b1y1 = b1.y - h1 * 0.5f, b1y2 = b1.y + h1 * 0.5f;
            float b2x1 = b2.x - w2 * 0.5f, b2x2 = b2.x + w2 * 0.5f;
            float b2y1 = b2.y - h2 * 0.5f, b2y2 = b2.y + h2 * 0.5f;

            float iw = fmaxf(fminf(b1x2, b2x2) - fmaxf(b1x1, b2x1), 0.0f);
            float ih = fmaxf(fminf(b1y2, b2y2) - fmaxf(b1y1, b2y1), 0.0f);
            float inter = iw * ih;
            float uni   = w1 * h1 + w2 * h2 - inter + EPSF;
            float iou   = inter / uni;

            float cw = fmaxf(b1x2, b2x2) - fminf(b1x1, b2x1);
            float ch = fmaxf(b1y2, b2y2) - fminf(b1y1, b2y1);
            float c2 = cw * cw + ch * ch + EPSF;

            float dx = b2x1 + b2x2 - b1x1 - b1x2;
            float dy = b2y1 + b2y2 - b1y1 - b1y2;
            float rho2 = (dx * dx + dy * dy) * 0.25f;

            float dat = atanf(w2 / h2) - atanf(w1 / h1);
            float v   = FOUR_PI2 * dat * dat;
            float alpha = v / (v - iou + (1.0f + EPSF));
            float ciou = iou - (rho2 / c2 + v * alpha);

            float t = 1.0f - ciou;                    // >= 0
            float pw = t * t * sqrtf(t);              // t^2.5
            float dw = fmaf(ALPHA_C, dens[i], 1.0f);
            float hw = 1.0f / (1.0f + expf(-5.0f * (0.5f - ciou)));
            accA = dw * hw * pw;
            accB = 1.0f / (w2 * h2 + 1e-7f);
        }
        float2 bs = block_reduce_sum2(accA, accB);
        if (threadIdx.x == 0) {
            g_partA[blockIdx.x] = bs.x;
            g_partB[blockIdx.x] = bs.y;
        }
    } else {
        // ---------------- contrastive term ----------------
        float accC = 0.0f;
        int lane = threadIdx.x & 31;
        int warp = threadIdx.x >> 5;
        int p = (blockIdx.x - locBlocks) * (blockDim.x >> 5) + warp;
        if (p < P) {
            int i = idx[2 * p];
            int j = idx[2 * p + 1];
            float4 bi = pred[i];
            float4 bj = pred[j];
            float piou = plain_iou(bi, bj);

            const float4* ei = (const float4*)(emb + (size_t)i * D);
            const float4* ej = (const float4*)(emb + (size_t)j * D);
            int D4 = D >> 2;
            float s = 0.0f;
            for (int c = lane; c < D4; c += 32) {
                float4 u = ei[c];
                float4 v = ej[c];
                float d0 = u.x - v.x, d1 = u.y - v.y;
                float d2 = u.z - v.z, d3 = u.w - v.w;
                s = fmaf(d0, d0, s); s = fmaf(d1, d1, s);
                s = fmaf(d2, d2, s); s = fmaf(d3, d3, s);
            }
            #pragma unroll
            for (int off = 16; off > 0; off >>= 1)
                s += __shfl_down_sync(0xffffffffu, s, off);
            if (lane == 0 && piou > TAU_C) {
                float d = sqrtf(s);
                float t = fmaxf(DELTA_C - d, 0.0f);
                accC = t * t;
            }
        }
        float2 bs = block_reduce_sum2(accC, 0.0f);
        int pb = blockIdx.x - locBlocks;
        if (threadIdx.x == 0) g_partC[pb] = bs.x;
    }
}

__global__ void dosa_finalize_kernel(float* __restrict__ out,
                                     int locBlocks, int pairBlocks,
                                     float invN2, float pairScale) {
    // single block, 128 threads
    float a = 0.0f, b = 0.0f, c = 0.0f;
    for (int k = threadIdx.x; k < locBlocks; k += blockDim.x) {
        a += g_partA[k];
        b += g_partB[k];
    }
    for (int k = threadIdx.x; k < pairBlocks; k += blockDim.x)
        c += g_partC[k];

    __shared__ float shA[4], shB[4], shC[4];
    int lane = threadIdx.x & 31;
    int warp = threadIdx.x >> 5;
    #pragma unroll
    for (int off = 16; off > 0; off >>= 1) {
        a += __shfl_down_sync(0xffffffffu, a, off);
        b += __shfl_down_sync(0xffffffffu, b, off);
        c += __shfl_down_sync(0xffffffffu, c, off);
    }
    if (lane == 0) { shA[warp] = a; shB[warp] = b; shC[warp] = c; }
    __syncthreads();
    if (warp == 0) {
        a = (threadIdx.x < 4) ? shA[threadIdx.x] : 0.0f;
        b = (threadIdx.x < 4) ? shB[threadIdx.x] : 0.0f;
        c = (threadIdx.x < 4) ? shC[threadIdx.x] : 0.0f;
        #pragma unroll
        for (int off = 2; off > 0; off >>= 1) {
            a += __shfl_down_sync(0xffffffffu, a, off);
            b += __shfl_down_sync(0xffffffffu, b, off);
            c += __shfl_down_sync(0xffffffffu, c, off);
        }
        if (threadIdx.x == 0)
            out[0] = a * b * invN2 + c * pairScale;
    }
}

extern "C" void kernel_launch(void* const* d_in, const int* in_sizes, int n_in,
                              void* d_out, int out_size) {
    const float4* pred = (const float4*)d_in[0];
    const float4* tgt  = (const float4*)d_in[1];
    const float*  emb  = (const float*)d_in[2];
    const float*  dens = (const float*)d_in[3];
    const int*    idx  = (const int*)d_in[4];
    float* out = (float*)d_out;

    int N = in_sizes[0] / 4;
    int D = in_sizes[2] / N;
    int P = in_sizes[4] / 2;

    int locBlocks   = (N + LOC_THREADS - 1) / LOC_THREADS;
    int warpsPerBlk = LOC_THREADS / 32;
    int pairBlocks  = (P + warpsPerBlk - 1) / warpsPerBlk;
    int nblocks = locBlocks + pairBlocks;

    dosa_fused_kernel<<<nblocks, LOC_THREADS>>>(pred, tgt, emb, dens, idx,
                                                N, D, P, locBlocks);

    float invN2 = 1.0f / ((float)N * (float)N);
    float pairScale = 0.5f / ((float)P + 1e-7f);
    dosa_finalize_kernel<<<1, 128>>>(out, locBlocks, pairBlocks,
                                     invN2, pairScale);
}

// round 3
// speedup vs baseline: 1.0360x; 1.0360x over previous
#include <cuda_runtime.h>
#include <math.h>

// ---------------------------------------------------------------------------
// DOSAConLoss — single-launch fused version.
//
// loss_loc factorizes (reference broadcasts (N,1)/(N,) -> (N,N) mean):
//   loss_loc = (Sum_i dw_i*hw_i*(1-ciou_i)^2.5) * (Sum_j 1/(area_j+1e-7)) / N^2
//
// Single kernel: 32 loc blocks + 13 pair blocks write partials; the LAST
// block to finish (device atomic counter) performs the final combine and
// resets the counter (graph-replayable, deterministic result).
// ---------------------------------------------------------------------------

#define EPSF        1e-7f
#define ALPHA_C     1.2f
#define TAU_C       0.3f
#define DELTA_C     1.0f
#define FOUR_PI2    0.40528473456935108577f   // 4/pi^2

#define LOC_THREADS 256
#define MAX_PART    1024

__device__ float g_partA[MAX_PART];   // loc numerator partials
__device__ float g_partB[MAX_PART];   // loc 1/area partials
__device__ float g_partC[MAX_PART];   // contrastive partials
__device__ unsigned int g_done = 0;   // completion counter (self-resetting)

// ---- fused block reduce of two floats (result valid in thread 0) ----
__device__ __forceinline__ float2 block_reduce_sum2(float a, float b) {
    __shared__ float shA[LOC_THREADS / 32];
    __shared__ float shB[LOC_THREADS / 32];
    int lane = threadIdx.x & 31;
    int warp = threadIdx.x >> 5;
    #pragma unroll
    for (int off = 16; off > 0; off >>= 1) {
        a += __shfl_down_sync(0xffffffffu, a, off);
        b += __shfl_down_sync(0xffffffffu, b, off);
    }
    if (lane == 0) { shA[warp] = a; shB[warp] = b; }
    __syncthreads();
    int nw = blockDim.x >> 5;
    a = (threadIdx.x < nw) ? shA[threadIdx.x] : 0.0f;
    b = (threadIdx.x < nw) ? shB[threadIdx.x] : 0.0f;
    if (warp == 0) {
        #pragma unroll
        for (int off = 16; off > 0; off >>= 1) {
            a += __shfl_down_sync(0xffffffffu, a, off);
            b += __shfl_down_sync(0xffffffffu, b, off);
        }
    }
    return make_float2(a, b);
}

__device__ __forceinline__ float plain_iou(float4 a, float4 b) {
    float a_x1 = a.x - a.z * 0.5f, a_x2 = a.x + a.z * 0.5f;
    float a_y1 = a.y - a.w * 0.5f, a_y2 = a.y + a.w * 0.5f;
    float b_x1 = b.x - b.z * 0.5f, b_x2 = b.x + b.z * 0.5f;
    float b_y1 = b.y - b.w * 0.5f, b_y2 = b.y + b.w * 0.5f;
    float iw = fmaxf(fminf(a_x2, b_x2) - fmaxf(a_x1, b_x1), 0.0f);
    float ih = fmaxf(fminf(a_y2, b_y2) - fmaxf(a_y1, b_y1), 0.0f);
    float inter = iw * ih;
    float uni = a.z * a.w + b.z * b.w - inter + EPSF;
    return inter / uni;
}

__global__ void dosa_onepass_kernel(const float4* __restrict__ pred,
                                    const float4* __restrict__ tgt,
                                    const float*  __restrict__ emb,
                                    const float*  __restrict__ dens,
                                    const int*    __restrict__ idx,
                                    float* __restrict__ out,
                                    int N, int D, int P,
                                    int locBlocks, int nblocks,
                                    float invN2, float pairScale) {
    // ---------------- phase 1: per-block partials ----------------
    if ((int)blockIdx.x < locBlocks) {
        float accA = 0.0f, accB = 0.0f;
        int i = blockIdx.x * blockDim.x + threadIdx.x;
        if (i < N) {
            float4 b1 = pred[i];
            float4 b2 = tgt[i];

            float w1 = b1.z, h1 = b1.w, w2 = b2.z, h2 = b2.w;
            float b1x1 = b1.x - w1 * 0.5f, b1x2 = b1.x + w1 * 0.5f;
            float b1y1 = b1.y - h1 * 0.5f, b1y2 = b1.y + h1 * 0.5f;
            float b2x1 = b2.x - w2 * 0.5f, b2x2 = b2.x + w2 * 0.5f;
            float b2y1 = b2.y - h2 * 0.5f, b2y2 = b2.y + h2 * 0.5f;

            float iw = fmaxf(fminf(b1x2, b2x2) - fmaxf(b1x1, b2x1), 0.0f);
            float ih = fmaxf(fminf(b1y2, b2y2) - fmaxf(b1y1, b2y1), 0.0f);
            float inter = iw * ih;
            float uni   = w1 * h1 + w2 * h2 - inter + EPSF;
            float iou   = inter / uni;

            float cw = fmaxf(b1x2, b2x2) - fminf(b1x1, b2x1);
            float ch = fmaxf(b1y2, b2y2) - fminf(b1y1, b2y1);
            float c2 = cw * cw + ch * ch + EPSF;

            float dx = b2x1 + b2x2 - b1x1 - b1x2;
            float dy = b2y1 + b2y2 - b1y1 - b1y2;
            float rho2 = (dx * dx + dy * dy) * 0.25f;

            float dat = atanf(w2 / h2) - atanf(w1 / h1);
            float v   = FOUR_PI2 * dat * dat;
            float alpha = v / (v - iou + (1.0f + EPSF));
            float ciou = iou - (rho2 / c2 + v * alpha);

            float t  = 1.0f - ciou;                   // >= 0
            float pw = t * t * sqrtf(t);              // t^2.5
            float dw = fmaf(ALPHA_C, dens[i], 1.0f);
            float hw = 1.0f / (1.0f + __expf(-5.0f * (0.5f - ciou)));
            accA = dw * hw * pw;
            accB = 1.0f / (w2 * h2 + 1e-7f);
        }
        float2 bs = block_reduce_sum2(accA, accB);
        if (threadIdx.x == 0) {
            g_partA[blockIdx.x] = bs.x;
            g_partB[blockIdx.x] = bs.y;
        }
    } else {
        float accC = 0.0f;
        int lane = threadIdx.x & 31;
        int warp = threadIdx.x >> 5;
        int p = (blockIdx.x - locBlocks) * (blockDim.x >> 5) + warp;
        if (p < P) {
            int i = idx[2 * p];
            int j = idx[2 * p + 1];
            float piou = plain_iou(pred[i], pred[j]);

            const float4* ei = (const float4*)(emb + (size_t)i * D);
            const float4* ej = (const float4*)(emb + (size_t)j * D);
            int D4 = D >> 2;
            float s = 0.0f;
            for (int c = lane; c < D4; c += 32) {
                float4 u = ei[c];
                float4 v = ej[c];
                float d0 = u.x - v.x, d1 = u.y - v.y;
                float d2 = u.z - v.z, d3 = u.w - v.w;
                s = fmaf(d0, d0, s); s = fmaf(d1, d1, s);
                s = fmaf(d2, d2, s); s = fmaf(d3, d3, s);
            }
            #pragma unroll
            for (int off = 16; off > 0; off >>= 1)
                s += __shfl_down_sync(0xffffffffu, s, off);
            if (lane == 0 && piou > TAU_C) {
                float d = sqrtf(s);
                float t = fmaxf(DELTA_C - d, 0.0f);
                accC = t * t;
            }
        }
        float2 bs = block_reduce_sum2(accC, 0.0f);
        if (threadIdx.x == 0) g_partC[blockIdx.x - locBlocks] = bs.x;
    }

    // ---------------- phase 2: last block finalizes ----------------
    __shared__ unsigned int s_isLast;
    __threadfence();                       // publish partials
    if (threadIdx.x == 0) {
        unsigned int prev = atomicAdd(&g_done, 1u);
        s_isLast = (prev == (unsigned int)(nblocks - 1));
    }
    __syncthreads();
    if (!s_isLast) return;

    __threadfence();                       // acquire all partials
    int pairBlocks = nblocks - locBlocks;
    float a = 0.0f, b = 0.0f, c = 0.0f;
    for (int k = threadIdx.x; k < locBlocks; k += blockDim.x) {
        a += g_partA[k];
        b += g_partB[k];
    }
    for (int k = threadIdx.x; k < pairBlocks; k += blockDim.x)
        c += g_partC[k];

    __shared__ float shA[LOC_THREADS / 32], shB[LOC_THREADS / 32],
                     shC[LOC_THREADS / 32];
    int lane = threadIdx.x & 31;
    int warp = threadIdx.x >> 5;
    #pragma unroll
    for (int off = 16; off > 0; off >>= 1) {
        a += __shfl_down_sync(0xffffffffu, a, off);
        b += __shfl_down_sync(0xffffffffu, b, off);
        c += __shfl_down_sync(0xffffffffu, c, off);
    }
    if (lane == 0) { shA[warp] = a; shB[warp] = b; shC[warp] = c; }
    __syncthreads();
    if (warp == 0) {
        int nw = blockDim.x >> 5;
        a = (threadIdx.x < nw) ? shA[threadIdx.x] : 0.0f;
        b = (threadIdx.x < nw) ? shB[threadIdx.x] : 0.0f;
        c = (threadIdx.x < nw) ? shC[threadIdx.x] : 0.0f;
        #pragma unroll
        for (int off = 4; off > 0; off >>= 1) {
            a += __shfl_down_sync(0xffffffffu, a, off);
            b += __shfl_down_sync(0xffffffffu, b, off);
            c += __shfl_down_sync(0xffffffffu, c, off);
        }
        if (threadIdx.x == 0) {
            out[0] = a * b * invN2 + c * pairScale;
            g_done = 0;                    // reset for next graph replay
        }
    }
}

extern "C" void kernel_launch(void* const* d_in, const int* in_sizes, int n_in,
                              void* d_out, int out_size) {
    const float4* pred = (const float4*)d_in[0];
    const float4* tgt  = (const float4*)d_in[1];
    const float*  emb  = (const float*)d_in[2];
    const float*  dens = (const float*)d_in[3];
    const int*    idx  = (const int*)d_in[4];
    float* out = (float*)d_out;

    int N = in_sizes[0] / 4;
    int D = in_sizes[2] / N;
    int P = in_sizes[4] / 2;

    int locBlocks   = (N + LOC_THREADS - 1) / LOC_THREADS;
    int warpsPerBlk = LOC_THREADS / 32;
    int pairBlocks  = (P + warpsPerBlk - 1) / warpsPerBlk;
    int nblocks = locBlocks + pairBlocks;

    float invN2 = 1.0f / ((float)N * (float)N);
    float pairScale = 0.5f / ((float)P + 1e-7f);

    dosa_onepass_kernel<<<nblocks, LOC_THREADS>>>(pred, tgt, emb, dens, idx,
                                                  out, N, D, P,
                                                  locBlocks, nblocks,
                                                  invN2, pairScale);
}

// round 4
// speedup vs baseline: 1.0627x; 1.0258x over previous
#include <cuda_runtime.h>
#include <math.h>

// ---------------------------------------------------------------------------
// DOSAConLoss — single-launch, min-critical-path version.
//
// loss_loc factorizes (reference broadcasts (N,1)/(N,) -> (N,N) mean):
//   loss_loc = (Sum_i dw_i*hw_i*(1-ciou_i)^2.5) * (Sum_j 1/(area_j+1e-7)) / N^2
//
// One kernel, 512-thread blocks: 16 loc blocks (1 box/thread) + 7 pair
// blocks (1 pair/warp). Each block release-publishes a partial via a single
// acq_rel atomic counter bump; the last block's warp 0 finalizes with a
// sync-free shuffle-broadcast + one parallel load round trip.
// ---------------------------------------------------------------------------

#define EPSF        1e-7f
#define ALPHA_C     1.2f
#define TAU_C       0.3f
#define DELTA_C     1.0f
#define FOUR_PI2    0.40528473456935108577f   // 4/pi^2

#define TPB         512
#define MAX_PART    512

__device__ float2 g_partAB[MAX_PART];   // loc partials (A = numer, B = 1/area)
__device__ float  g_partC[MAX_PART];    // contrastive partials
__device__ unsigned int g_done = 0;     // completion counter (self-resetting)

// release-increment; returns previous value, acquire semantics on return
__device__ __forceinline__ unsigned int atomic_inc_acq_rel(unsigned int* p) {
    unsigned int prev;
    asm volatile("atom.acq_rel.gpu.add.u32 %0, [%1], 1;"
                 : "=r"(prev) : "l"(p) : "memory");
    return prev;
}

__device__ __forceinline__ unsigned int ld_acquire(const unsigned int* p) {
    unsigned int v;
    asm volatile("ld.acquire.gpu.u32 %0, [%1];" : "=r"(v) : "l"(p) : "memory");
    return v;
}

// ---- fused block reduce of two floats (result valid in thread 0) ----
__device__ __forceinline__ float2 block_reduce_sum2(float a, float b) {
    __shared__ float shA[TPB / 32];
    __shared__ float shB[TPB / 32];
    int lane = threadIdx.x & 31;
    int warp = threadIdx.x >> 5;
    #pragma unroll
    for (int off = 16; off > 0; off >>= 1) {
        a += __shfl_down_sync(0xffffffffu, a, off);
        b += __shfl_down_sync(0xffffffffu, b, off);
    }
    if (lane == 0) { shA[warp] = a; shB[warp] = b; }
    __syncthreads();
    int nw = blockDim.x >> 5;            // 16
    a = (threadIdx.x < nw) ? shA[threadIdx.x] : 0.0f;
    b = (threadIdx.x < nw) ? shB[threadIdx.x] : 0.0f;
    if (warp == 0) {
        #pragma unroll
        for (int off = 8; off > 0; off >>= 1) {
            a += __shfl_down_sync(0xffffffffu, a, off);
            b += __shfl_down_sync(0xffffffffu, b, off);
        }
    }
    return make_float2(a, b);
}

__global__ __launch_bounds__(TPB)
void dosa_onepass_kernel(const float4* __restrict__ pred,
                         const float4* __restrict__ tgt,
                         const float*  __restrict__ emb,
                         const float*  __restrict__ dens,
                         const int2*   __restrict__ idx,
                         float* __restrict__ out,
                         int N, int D, int P,
                         int locBlocks, int nblocks,
                         float invN2, float pairScale) {
    // ---------------- phase 1: per-block partials ----------------
    if ((int)blockIdx.x < locBlocks) {
        float accA = 0.0f, accB = 0.0f;
        int i = blockIdx.x * TPB + threadIdx.x;
        if (i < N) {
            float4 b1 = pred[i];
            float4 b2 = tgt[i];
            float dv = dens[i];

            float w1 = b1.z, h1 = b1.w, w2 = b2.z, h2 = b2.w;
            float b1x1 = b1.x - w1 * 0.5f, b1x2 = b1.x + w1 * 0.5f;
            float b1y1 = b1.y - h1 * 0.5f, b1y2 = b1.y + h1 * 0.5f;
            float b2x1 = b2.x - w2 * 0.5f, b2x2 = b2.x + w2 * 0.5f;
            float b2y1 = b2.y - h2 * 0.5f, b2y2 = b2.y + h2 * 0.5f;

            float iw = fmaxf(fminf(b1x2, b2x2) - fmaxf(b1x1, b2x1), 0.0f);
            float ih = fmaxf(fminf(b1y2, b2y2) - fmaxf(b1y1, b2y1), 0.0f);
            float inter = iw * ih;
            float uni   = w1 * h1 + w2 * h2 - inter + EPSF;
            float iou   = __fdividef(inter, uni);

            float cw = fmaxf(b1x2, b2x2) - fminf(b1x1, b2x1);
            float ch = fmaxf(b1y2, b2y2) - fminf(b1y1, b2y1);
            float c2 = cw * cw + ch * ch + EPSF;

            float dx = b2x1 + b2x2 - b1x1 - b1x2;
            float dy = b2y1 + b2y2 - b1y1 - b1y2;
            float rho2 = (dx * dx + dy * dy) * 0.25f;

            float dat = atanf(__fdividef(w2, h2)) - atanf(__fdividef(w1, h1));
            float v   = FOUR_PI2 * dat * dat;
            float alpha = __fdividef(v, v - iou + (1.0f + EPSF));
            float ciou = iou - (__fdividef(rho2, c2) + v * alpha);

            float t  = 1.0f - ciou;                   // >= 0
            float pw = t * t * sqrtf(t);              // t^2.5
            float dw = fmaf(ALPHA_C, dv, 1.0f);
            float hw = __fdividef(1.0f, 1.0f + __expf(-5.0f * (0.5f - ciou)));
            accA = dw * hw * pw;
            accB = __fdividef(1.0f, w2 * h2 + 1e-7f);
        }
        float2 bs = block_reduce_sum2(accA, accB);
        if (threadIdx.x == 0) g_partAB[blockIdx.x] = bs;
    } else {
        float accC = 0.0f;
        int lane = threadIdx.x & 31;
        int warp = threadIdx.x >> 5;
        int p = (blockIdx.x - locBlocks) * (TPB >> 5) + warp;
        if (p < P) {
            int2 ij = idx[p];                         // first load, issues early
            int i = ij.x, j = ij.y;

            // issue all gathers before any dependent math
            float4 bi = pred[i];
            float4 bj = pred[j];
            const float4* ei = (const float4*)(emb + (size_t)i * D);
            const float4* ej = (const float4*)(emb + (size_t)j * D);
            int D4 = D >> 2;
            float s = 0.0f;
            for (int c = lane; c < D4; c += 32) {
                float4 u = ei[c];
                float4 v = ej[c];
                float d0 = u.x - v.x, d1 = u.y - v.y;
                float d2 = u.z - v.z, d3 = u.w - v.w;
                s = fmaf(d0, d0, s); s = fmaf(d1, d1, s);
                s = fmaf(d2, d2, s); s = fmaf(d3, d3, s);
            }
            #pragma unroll
            for (int off = 16; off > 0; off >>= 1)
                s += __shfl_down_sync(0xffffffffu, s, off);

            float a_x1 = bi.x - bi.z * 0.5f, a_x2 = bi.x + bi.z * 0.5f;
            float a_y1 = bi.y - bi.w * 0.5f, a_y2 = bi.y + bi.w * 0.5f;
            float b_x1 = bj.x - bj.z * 0.5f, b_x2 = bj.x + bj.z * 0.5f;
            float b_y1 = bj.y - bj.w * 0.5f, b_y2 = bj.y + bj.w * 0.5f;
            float iw = fmaxf(fminf(a_x2, b_x2) - fmaxf(a_x1, b_x1), 0.0f);
            float ih = fmaxf(fminf(a_y2, b_y2) - fmaxf(a_y1, b_y1), 0.0f);
            float inter = iw * ih;
            float uni = bi.z * bi.w + bj.z * bj.w - inter + EPSF;
            float piou = __fdividef(inter, uni);

            if (lane == 0 && piou > TAU_C) {
                float d = sqrtf(s);
                float t = fmaxf(DELTA_C - d, 0.0f);
                accC = t * t;
            }
        }
        float2 bs = block_reduce_sum2(accC, 0.0f);
        if (threadIdx.x == 0) g_partC[blockIdx.x - locBlocks] = bs.x;
    }

    // ---------------- phase 2: last block's warp 0 finalizes -------------
    if ((threadIdx.x >> 5) != 0) return;   // only warp 0 participates

    int lane = threadIdx.x;                // 0..31
    int last = 0;
    if (lane == 0) {
        unsigned int prev = atomic_inc_acq_rel(&g_done);
        last = (prev == (unsigned int)(nblocks - 1));
    }
    last = __shfl_sync(0xffffffffu, last, 0);
    if (!last) return;

    (void)ld_acquire(&g_done);             // acquire on reading lanes

    int pairBlocks = nblocks - locBlocks;
    float a = 0.0f, b = 0.0f, c = 0.0f;
    for (int k = lane; k < locBlocks; k += 32) {
        float2 ab = g_partAB[k];
        a += ab.x; b += ab.y;
    }
    for (int k = lane; k < pairBlocks; k += 32)
        c += g_partC[k];

    #pragma unroll
    for (int off = 16; off > 0; off >>= 1) {
        a += __shfl_down_sync(0xffffffffu, a, off);
        b += __shfl_down_sync(0xffffffffu, b, off);
        c += __shfl_down_sync(0xffffffffu, c, off);
    }
    if (lane == 0) {
        out[0] = a * b * invN2 + c * pairScale;
        g_done = 0;                        // reset for next graph replay
    }
}

extern "C" void kernel_launch(void* const* d_in, const int* in_sizes, int n_in,
                              void* d_out, int out_size) {
    const float4* pred = (const float4*)d_in[0];
    const float4* tgt  = (const float4*)d_in[1];
    const float*  emb  = (const float*)d_in[2];
    const float*  dens = (const float*)d_in[3];
    const int2*   idx  = (const int2*)d_in[4];
    float* out = (float*)d_out;

    int N = in_sizes[0] / 4;
    int D = in_sizes[2] / N;
    int P = in_sizes[4] / 2;

    int locBlocks   = (N + TPB - 1) / TPB;            // 16
    int warpsPerBlk = TPB / 32;                       // 16
    int pairBlocks  = (P + warpsPerBlk - 1) / warpsPerBlk;  // 7
    int nblocks = locBlocks + pairBlocks;             // 23

    float invN2 = 1.0f / ((float)N * (float)N);
    float pairScale = 0.5f / ((float)P + 1e-7f);

    dosa_onepass_kernel<<<nblocks, TPB>>>(pred, tgt, emb, dens, idx,
                                          out, N, D, P,
                                          locBlocks, nblocks,
                                          invN2, pairScale);
}